// round 6
// baseline (speedup 1.0000x reference)
#include <cuda_runtime.h>

// RoiPoolingConv: ROI-Align bilinear pooling, POOL=7
// img:  (8, 64, 64, 1024) float32, NHWC (channels contiguous)
// rois: (32, 4) int32  [x, y, w, h]
// out:  flat index ((r*8 + b)*7 + py)*7 + px, 1024 channels contiguous
//
// R6: one tile per 128-thread CTA, each thread covers channel chunks t and
// t+128 (float4 units) -> 8 independent LDG.128 per thread (same MLP as the
// 2-tile version) but with a single tile_addr computation (fewer regs, less
// ALU) and finer-grained CTAs (better tail/load balance). __stcs stores keep
// the output stream from polluting L2.

#define N_ROIS 32
#define N_BATCH 8
#define POOLP 7
#define CH 1024
#define CH4 (CH / 4)          // 256 float4 per row
#define IMG_W 64
#define IMG_H 64
#define N_TILES (N_ROIS * N_BATCH * POOLP * POOLP)   // 12544

struct TileAddr {
    const float4* p00;
    const float4* p01;
    const float4* p10;
    const float4* p11;
    float wx, wy;
};

__device__ __forceinline__ TileAddr tile_addr(const float* __restrict__ img,
                                              const int* __restrict__ rois,
                                              int flat)
{
    const int px = flat % POOLP;
    const int py = (flat / POOLP) % POOLP;
    const int b  = (flat / (POOLP * POOLP)) % N_BATCH;
    const int r  = flat / (POOLP * POOLP * N_BATCH);

    const int rx = rois[r * 4 + 0];
    const int ry = rois[r * 4 + 1];
    const int rw = rois[r * 4 + 2];
    const int rh = rois[r * 4 + 3];

    // coord = (p+0.5)*(size/POOL) - 0.5 (matches reference _edge)
    const float cx = ((float)px + 0.5f) * ((float)rw / (float)POOLP) - 0.5f;
    const float fx = floorf(cx);
    const int lox = max((int)fx, 0);
    const int hix = min(max((int)ceilf(cx), 0), rw - 1);
    const int x0 = rx + lox;
    const int x1 = rx + hix;

    const float cy = ((float)py + 0.5f) * ((float)rh / (float)POOLP) - 0.5f;
    const float fy = floorf(cy);
    const int loy = max((int)fy, 0);
    const int hiy = min(max((int)ceilf(cy), 0), rh - 1);
    const int y0 = ry + loy;
    const int y1 = ry + hiy;

    const size_t base_b = (size_t)b * IMG_H * IMG_W * CH;

    TileAddr ta;
    ta.p00 = (const float4*)(img + base_b + ((size_t)y0 * IMG_W + x0) * CH);
    ta.p01 = (const float4*)(img + base_b + ((size_t)y0 * IMG_W + x1) * CH);
    ta.p10 = (const float4*)(img + base_b + ((size_t)y1 * IMG_W + x0) * CH);
    ta.p11 = (const float4*)(img + base_b + ((size_t)y1 * IMG_W + x1) * CH);
    ta.wx = cx - fx;
    ta.wy = cy - fy;
    return ta;
}

__device__ __forceinline__ float4 lerp4(float4 a, float4 b, float4 c, float4 d,
                                        float wx, float wy)
{
    float4 res;
    float top, bot;
    top = a.x + (b.x - a.x) * wx;
    bot = c.x + (d.x - c.x) * wx;
    res.x = top + (bot - top) * wy;
    top = a.y + (b.y - a.y) * wx;
    bot = c.y + (d.y - c.y) * wx;
    res.y = top + (bot - top) * wy;
    top = a.z + (b.z - a.z) * wx;
    bot = c.z + (d.z - c.z) * wx;
    res.z = top + (bot - top) * wy;
    top = a.w + (b.w - a.w) * wx;
    bot = c.w + (d.w - c.w) * wx;
    res.w = top + (bot - top) * wy;
    return res;
}

__global__ void __launch_bounds__(128) roi_align_kernel_v6(
    const float* __restrict__ img,
    const int*   __restrict__ rois,
    float*       __restrict__ out)
{
    const int flat = blockIdx.x;
    const int t0 = threadIdx.x;          // channel chunk 0: float4 index t0
    const int t1 = t0 + 128;             // channel chunk 1: float4 index t0+128

    const TileAddr ta = tile_addr(img, rois, flat);

    // 8 independent LDG.128 per thread, issued back-to-back
    const float4 a0 = ta.p00[t0];
    const float4 b0 = ta.p01[t0];
    const float4 c0 = ta.p10[t0];
    const float4 d0 = ta.p11[t0];
    const float4 a1 = ta.p00[t1];
    const float4 b1 = ta.p01[t1];
    const float4 c1 = ta.p10[t1];
    const float4 d1 = ta.p11[t1];

    float4* o = (float4*)(out + (size_t)flat * CH);

    __stcs(o + t0, lerp4(a0, b0, c0, d0, ta.wx, ta.wy));
    __stcs(o + t1, lerp4(a1, b1, c1, d1, ta.wx, ta.wy));
}

extern "C" void kernel_launch(void* const* d_in, const int* in_sizes, int n_in,
                              void* d_out, int out_size)
{
    const float* img  = (const float*)d_in[0];
    const int*   rois = (const int*)d_in[1];
    float*       out  = (float*)d_out;

    roi_align_kernel_v6<<<N_TILES, 128>>>(img, rois, out);
}